// round 8
// baseline (speedup 1.0000x reference)
#include <cuda_runtime.h>

#define XS    128
#define BATCH 8
#define MPTS  500000
#define NPLANES (BATCH * XS)                 // 1024
#define NQUART  (NPLANES * 4)                // 4096 quarter-planes
#define GRID_ELEMS (BATCH * XS * XS * XS)    // 16,777,216 floats = 64 MiB
#define TPB_SCAT (MPTS / 8)                  // 62,500 scatter threads per batch
#define SCAT_BLK 245                         // ceil(62500/256)
#define RED_BLK  256                         // 64 plane-pairs * 4 quarters
#define GRP_BLK  (SCAT_BLK + RED_BLK)        // 501 blocks per batch
#define TOTAL_BLK (BATCH * GRP_BLK)          // 4008

// Scratch (device globals: zero-initialized at load; all self-resetting)
__device__ float g_grid[GRID_ELEMS];
__device__ int   g_done[NQUART];             // zero-protocol read counters
__device__ unsigned g_scnt[BATCH];           // scatter blocks done per batch
__device__ unsigned g_rcnt[BATCH];           // reduce blocks done per batch
__device__ float g_acc_tv[BATCH];
__device__ float g_acc_mse[BATCH];

// ---- scoped atomics (cg::grid_sync-style signaling) ----
__device__ __forceinline__ void red_release_add(unsigned* p, unsigned v) {
    asm volatile("red.release.gpu.add.u32 [%0], %1;" :: "l"(p), "r"(v) : "memory");
}
__device__ __forceinline__ unsigned atom_acqrel_add(unsigned* p, unsigned v) {
    unsigned r;
    asm volatile("atom.acq_rel.gpu.add.u32 %0, [%1], %2;"
                 : "=r"(r) : "l"(p), "r"(v) : "memory");
    return r;
}
__device__ __forceinline__ unsigned ld_acquire(const unsigned* p) {
    unsigned r;
    asm volatile("ld.acquire.gpu.u32 %0, [%1];" : "=r"(r) : "l"(p) : "memory");
    return r;
}
__device__ __forceinline__ float ldf_acquire(const float* p) {
    float r;
    asm volatile("ld.acquire.gpu.f32 %0, [%1];" : "=f"(r) : "l"(p) : "memory");
    return r;
}

// ---------------------------------------------------------------------------
__device__ __forceinline__ void diff4(const float4& a, const float4& b,
                                      float& tv, float& mse) {
    float d0 = b.x - a.x, d1 = b.y - a.y, d2 = b.z - a.z, d3 = b.w - a.w;
    tv  += fabsf(d0) + fabsf(d1) + fabsf(d2) + fabsf(d3);
    mse += d0 * d0 + d1 * d1 + d2 * d2 + d3 * d3;
}
__device__ __forceinline__ void kdiffs(const float4& c, bool cross,
                                       float& tv, float& mse) {
    float d0 = c.y - c.x, d1 = c.z - c.y, d2 = c.w - c.z;
    tv  += fabsf(d0) + fabsf(d1) + fabsf(d2);
    mse += d0 * d0 + d1 * d1 + d2 * d2;
    float nx = __shfl_down_sync(0xffffffffu, c.x, 1);
    if (cross) { float d3 = nx - c.w; tv += fabsf(d3); mse += d3 * d3; }
}
__device__ __forceinline__ void plane_kj(const float4 c[4], const float4& jb,
                                         bool has_jb, bool crossk,
                                         float& tv, float& mse) {
    #pragma unroll
    for (int r = 0; r < 4; r++) kdiffs(c[r], crossk, tv, mse);
    diff4(c[0], c[1], tv, mse);
    diff4(c[1], c[2], tv, mse);
    diff4(c[2], c[3], tv, mse);
    if (has_jb) diff4(c[3], jb, tv, mse);
}
__device__ __forceinline__ void zero_quarter(int qidx, int tid) {
    float4* gw = (float4*)g_grid;
    const long qb = (long)qidx << 10;
    const float4 z = make_float4(0.f, 0.f, 0.f, 0.f);
    #pragma unroll
    for (int it = 0; it < 4; ++it)
        gw[qb + it * 256 + tid] = z;
    if (tid == 0) g_done[qidx] = 0;
}

// ---------------------------------------------------------------------------
// ONE kernel, two roles, interleaved per batch: [245 scatter][256 reduce] x 8.
// Reducers of batch b spin (acquire + nanosleep) on g_scnt[b]==245, then
// reduce + re-zero while later batches scatter. d_out written by the last
// reducer per batch (acq_rel counted), from release-published accumulators.
// ---------------------------------------------------------------------------
__global__ void __launch_bounds__(256, 6) fused_kernel(
        const int4*   __restrict__ idx4,
        const float4* __restrict__ val4,
        float*        __restrict__ d_out) {
    const int grp = blockIdx.x / GRP_BLK;          // batch 0..7
    const int r   = blockIdx.x - grp * GRP_BLK;

    // ================= SCATTER ROLE =================
    if (r < SCAT_BLK) {
        int t = r * 256 + threadIdx.x;             // 0..62719
        if (t < TPB_SCAT) {
            long base = (long)grp << 21;
            long p0   = (long)grp * MPTS + (long)t * 8;
            int4 a[6];
            #pragma unroll
            for (int s = 0; s < 6; s++) a[s] = __ldcs(&idx4[(p0 * 3) / 4 + s]);
            float4 v0 = __ldcs(&val4[p0 / 4 + 0]);
            float4 v1 = __ldcs(&val4[p0 / 4 + 1]);
            const int* ai = (const int*)a;
            float vals[8] = { v0.x, v0.y, v0.z, v0.w, v1.x, v1.y, v1.z, v1.w };
            #pragma unroll
            for (int s = 0; s < 8; s++) {
                long off = base + ((long)ai[3 * s] << 14) + (ai[3 * s + 1] << 7)
                                + ai[3 * s + 2];
                atomicAdd(&g_grid[off], vals[s]);
            }
        }
        __syncthreads();                           // all REDs program-ordered
        if (threadIdx.x == 0) red_release_add(&g_scnt[grp], 1u);
        return;
    }

    // ================= REDUCE ROLE =================
    const int local = r - SCAT_BLK;                // 0..255
    const int lg    = local >> 2;                  // plane-pair in batch, 0..63
    const int q     = local & 3;
    const int p0    = grp * XS + lg * 2;           // even global plane
    const int i0    = lg * 2;                      // 0..126 even
    const int lane  = threadIdx.x & 31;
    const int wg    = threadIdx.x >> 5;
    const int jrow0 = q * 32 + wg * 4;
    const bool has_jb = (jrow0 + 4) < XS;
    const bool crossk = (lane != 31);
    const float4* __restrict__ g4 = (const float4*)g_grid;

    // wait for this batch's scatter (acquire pairs with scatter's release)
    if (threadIdx.x == 0) {
        while (ld_acquire(&g_scnt[grp]) < SCAT_BLK) __nanosleep(128);
    }
    __syncthreads();

    const long pb0 = (long)p0 << 12;
    const int  fo  = jrow0 * 32 + lane;
    const float4 z = make_float4(0.f, 0.f, 0.f, 0.f);

    float tv = 0.f, mse = 0.f;
    float4 c[4], n[4];

    #pragma unroll
    for (int rr = 0; rr < 4; rr++) c[rr] = g4[pb0 + fo + rr * 32];
    float4 jb0 = has_jb ? g4[pb0 + fo + 128] : z;
    plane_kj(c, jb0, has_jb, crossk, tv, mse);

    const long pb1 = pb0 + 4096;
    #pragma unroll
    for (int rr = 0; rr < 4; rr++) n[rr] = g4[pb1 + fo + rr * 32];
    #pragma unroll
    for (int rr = 0; rr < 4; rr++) diff4(c[rr], n[rr], tv, mse);
    float4 jb1 = has_jb ? g4[pb1 + fo + 128] : z;
    plane_kj(n, jb1, has_jb, crossk, tv, mse);

    const bool has_ext = (i0 < XS - 2);
    if (has_ext) {
        const long pb2 = pb1 + 4096;
        #pragma unroll
        for (int rr = 0; rr < 4; rr++) {
            float4 e = g4[pb2 + fo + rr * 32];
            diff4(n[rr], e, tv, mse);
        }
    }

    // block reduce -> thread 0 holds block partials
    #pragma unroll
    for (int off = 16; off > 0; off >>= 1) {
        tv  += __shfl_down_sync(0xffffffffu, tv,  off);
        mse += __shfl_down_sync(0xffffffffu, mse, off);
    }
    __shared__ float stv[8], smse[8];
    if (lane == 0) { stv[wg] = tv; smse[wg] = mse; }
    __syncthreads();
    float bptv = 0.f, bpmse = 0.f;
    if (threadIdx.x == 0) {
        #pragma unroll
        for (int s = 0; s < 8; s++) { bptv += stv[s]; bpmse += smse[s]; }
    }

    // ---- quarter-granular zero protocol (loads all consumed above) ----
    __shared__ int zmask;
    if (threadIdx.x == 0) zmask = 0;
    __syncthreads();
    if (threadIdx.x == 0) {
        int m = 0;
        int q0 = (p0 << 2) + q;
        int q1 = ((p0 + 1) << 2) + q;
        int tgt0 = 1 + (q > 0 ? 1 : 0) + (i0 > 0 ? 1 : 0);
        int tgt1 = 1 + (q > 0 ? 1 : 0);
        if (atomicAdd(&g_done[q0], 1) + 1 == tgt0) m |= 1;
        if (atomicAdd(&g_done[q1], 1) + 1 == tgt1) m |= 2;
        if (q < 3) {
            int j0 = (p0 << 2) + q + 1;
            int j1 = ((p0 + 1) << 2) + q + 1;
            if (atomicAdd(&g_done[j0], 1) + 1 == 2 + (i0 > 0 ? 1 : 0)) m |= 4;
            if (atomicAdd(&g_done[j1], 1) + 1 == 2) m |= 8;
        }
        if (has_ext) {
            int e0 = ((p0 + 2) << 2) + q;
            if (atomicAdd(&g_done[e0], 1) + 1 == 2 + (q > 0 ? 1 : 0)) m |= 16;
        }
        zmask = m;
    }
    __syncthreads();
    int m = zmask;
    if (m & 1)  zero_quarter((p0 << 2) + q,           threadIdx.x);
    if (m & 2)  zero_quarter(((p0 + 1) << 2) + q,     threadIdx.x);
    if (m & 4)  zero_quarter((p0 << 2) + q + 1,       threadIdx.x);
    if (m & 8)  zero_quarter(((p0 + 1) << 2) + q + 1, threadIdx.x);
    if (m & 16) zero_quarter(((p0 + 2) << 2) + q,     threadIdx.x);

    // ---- publish partials; last reducer of batch finalizes d_out ----
    if (threadIdx.x == 0) {
        atomicAdd(&g_acc_tv[grp],  bptv);           // relaxed
        atomicAdd(&g_acc_mse[grp], bpmse);
        unsigned prev = atom_acqrel_add(&g_rcnt[grp], 1u);  // release my adds
        if (prev == RED_BLK - 1) {                  // acquire all 256 adds
            float ttv  = ldf_acquire(&g_acc_tv[grp]);
            float tmse = ldf_acquire(&g_acc_mse[grp]);
            const float tv_norm  = 1.f / (float)(XS * XS * XS);
            const float mse_norm = 1.f / (float)(2 * XS * XS - 2 * XS);
            d_out[grp]         = ttv  * tv_norm;
            d_out[BATCH + grp] = tmse * mse_norm;
            // self-reset for next graph replay
            g_acc_tv[grp]  = 0.f;
            g_acc_mse[grp] = 0.f;
            g_rcnt[grp] = 0u;
            g_scnt[grp] = 0u;
        }
    }
}

// ---------------------------------------------------------------------------
extern "C" void kernel_launch(void* const* d_in, const int* in_sizes, int n_in,
                              void* d_out, int out_size) {
    const int*   indices = (const int*)d_in[0];    // (B, M, 3) int32
    const float* values  = (const float*)d_in[1];  // (B, M) float32
    float* out = (float*)d_out;                    // (2, B) float32

    fused_kernel<<<TOTAL_BLK, 256>>>((const int4*)indices,
                                     (const float4*)values, out);
}

// round 9
// speedup vs baseline: 1.2140x; 1.2140x over previous
#include <cuda_runtime.h>

#define XS    128
#define BATCH 8
#define MPTS  500000
#define NQUART  (BATCH * XS * 4)             // 4096 quarter-planes
#define GRID_ELEMS (BATCH * XS * XS * XS)    // 64 MiB
#define TPB_SCAT (MPTS / 8)                  // 62,500 scatter threads / batch
#define SCAT_BLK_B 245                       // ceil(62500/256)
#define SCAT_BLKS (BATCH * SCAT_BLK_B)       // 1960
#define RED_BLK_B 128                        // 32 i-chunks x 4 quarters
#define TOTAL_BLK (SCAT_BLKS + BATCH * RED_BLK_B)  // 2984

// Device scratch (zero-init at load; every counter self-resets per call)
__device__ float g_grid[GRID_ELEMS];
__device__ int   g_done[NQUART];
__device__ unsigned g_scnt[BATCH];
__device__ unsigned g_rcnt[BATCH];
__device__ float g_acc_tv[BATCH];
__device__ float g_acc_mse[BATCH];

// ---- scoped signaling ----
__device__ __forceinline__ void red_release_add(unsigned* p, unsigned v) {
    asm volatile("red.release.gpu.add.u32 [%0], %1;" :: "l"(p), "r"(v) : "memory");
}
__device__ __forceinline__ unsigned atom_acqrel_add(unsigned* p, unsigned v) {
    unsigned r;
    asm volatile("atom.acq_rel.gpu.add.u32 %0, [%1], %2;"
                 : "=r"(r) : "l"(p), "r"(v) : "memory");
    return r;
}
__device__ __forceinline__ unsigned ld_acquire(const unsigned* p) {
    unsigned r;
    asm volatile("ld.acquire.gpu.u32 %0, [%1];" : "=r"(r) : "l"(p) : "memory");
    return r;
}
__device__ __forceinline__ float ldf_acquire(const float* p) {
    float r;
    asm volatile("ld.acquire.gpu.f32 %0, [%1];" : "=f"(r) : "l"(p) : "memory");
    return r;
}

// ---- reduce helpers ----
__device__ __forceinline__ void diff4(const float4& a, const float4& b,
                                      float& tv, float& mse) {
    float d0 = b.x - a.x, d1 = b.y - a.y, d2 = b.z - a.z, d3 = b.w - a.w;
    tv  += fabsf(d0) + fabsf(d1) + fabsf(d2) + fabsf(d3);
    mse += d0 * d0 + d1 * d1 + d2 * d2 + d3 * d3;
}
__device__ __forceinline__ void kdiffs(const float4& c, bool cross,
                                       float& tv, float& mse) {
    float d0 = c.y - c.x, d1 = c.z - c.y, d2 = c.w - c.z;
    tv  += fabsf(d0) + fabsf(d1) + fabsf(d2);
    mse += d0 * d0 + d1 * d1 + d2 * d2;
    float nx = __shfl_down_sync(0xffffffffu, c.x, 1);
    if (cross) { float d3 = nx - c.w; tv += fabsf(d3); mse += d3 * d3; }
}
__device__ __forceinline__ void plane_kj(const float4 c[4], const float4& jb,
                                         bool has_jb, bool crossk,
                                         float& tv, float& mse) {
    #pragma unroll
    for (int r = 0; r < 4; r++) kdiffs(c[r], crossk, tv, mse);
    diff4(c[0], c[1], tv, mse);
    diff4(c[1], c[2], tv, mse);
    diff4(c[2], c[3], tv, mse);
    if (has_jb) diff4(c[3], jb, tv, mse);
}
__device__ __forceinline__ void zero_quarter(int qidx, int tid) {
    float4* gw = (float4*)g_grid;
    const long qb = (long)qidx << 10;
    const float4 z = make_float4(0.f, 0.f, 0.f, 0.f);
    #pragma unroll
    for (int it = 0; it < 4; ++it)
        gw[qb + it * 256 + tid] = z;
    if (tid == 0) g_done[qidx] = 0;
}

// ---------------------------------------------------------------------------
// Fused kernel, TAIL layout: bids [0,1960) scatter (batch-major), bids
// [1960,2984) reducers (batch-major). Reducers become resident only after
// ~55%+ of scatter retires, so their batch is already complete (no slot
// waste), while they overlap the scatter drain.
// ---------------------------------------------------------------------------
__global__ void __launch_bounds__(256) fused_kernel(
        const int4*   __restrict__ idx4,
        const float4* __restrict__ val4,
        float*        __restrict__ d_out) {

    // ================= SCATTER ROLE =================
    if (blockIdx.x < SCAT_BLKS) {
        int b = blockIdx.x / SCAT_BLK_B;
        int t = (blockIdx.x - b * SCAT_BLK_B) * 256 + threadIdx.x;
        if (t < TPB_SCAT) {
            long base = (long)b << 21;
            long p0   = (long)b * MPTS + (long)t * 8;
            int4 a[6];
            #pragma unroll
            for (int s = 0; s < 6; s++) a[s] = __ldcs(&idx4[(p0 * 3) / 4 + s]);
            float4 v0 = __ldcs(&val4[p0 / 4 + 0]);
            float4 v1 = __ldcs(&val4[p0 / 4 + 1]);
            const int* ai = (const int*)a;
            float vals[8] = { v0.x, v0.y, v0.z, v0.w, v1.x, v1.y, v1.z, v1.w };
            #pragma unroll
            for (int s = 0; s < 8; s++) {
                long off = base + ((long)ai[3 * s] << 14) + (ai[3 * s + 1] << 7)
                                + ai[3 * s + 2];
                atomicAdd(&g_grid[off], vals[s]);
            }
        }
        __syncthreads();
        if (threadIdx.x == 0) red_release_add(&g_scnt[b], 1u);
        return;
    }

    // ================= REDUCE ROLE (i-chained 4-plane chunk) ==============
    const int rb    = blockIdx.x - SCAT_BLKS;      // 0..1023, batch-major
    const int b     = rb >> 7;
    const int local = rb & 127;
    const int ic    = local >> 2;                  // i-chunk 0..31
    const int q     = local & 3;                   // quarter (j-strip of 32)
    const int p0    = b * XS + ic * 4;             // first owned plane
    const int lane  = threadIdx.x & 31;
    const int wg    = threadIdx.x >> 5;
    const int jrow0 = q * 32 + wg * 4;
    const bool has_jb = (jrow0 + 4) < XS;          // false only q==3 && wg==7
    const bool crossk = (lane != 31);
    const float4* __restrict__ g4 = (const float4*)g_grid;

    // wait for this batch's scatter (usually already complete on arrival)
    if (threadIdx.x == 0) {
        while (ld_acquire(&g_scnt[b]) < SCAT_BLK_B) __nanosleep(64);
    }
    __syncthreads();

    const long pb = (long)p0 << 12;
    const int  fo = jrow0 * 32 + lane;
    const float4 z = make_float4(0.f, 0.f, 0.f, 0.f);

    float tv = 0.f, mse = 0.f;
    float4 c[4], n[4];

    #pragma unroll
    for (int r = 0; r < 4; r++) c[r] = g4[pb + fo + r * 32];
    {
        float4 jb = has_jb ? g4[pb + fo + 128] : z;
        plane_kj(c, jb, has_jb, crossk, tv, mse);
    }
    #pragma unroll
    for (int t = 1; t < 4; ++t) {
        const long pbt = pb + (long)t * 4096;
        #pragma unroll
        for (int r = 0; r < 4; r++) n[r] = g4[pbt + fo + r * 32];
        #pragma unroll
        for (int r = 0; r < 4; r++) diff4(c[r], n[r], tv, mse);
        float4 jb = has_jb ? g4[pbt + fo + 128] : z;
        plane_kj(n, jb, has_jb, crossk, tv, mse);
        #pragma unroll
        for (int r = 0; r < 4; r++) c[r] = n[r];
    }
    if (ic < 31) {                                 // seam plane p0+4
        const long pbs = pb + 4L * 4096;
        #pragma unroll
        for (int r = 0; r < 4; r++) {
            float4 e = g4[pbs + fo + r * 32];
            diff4(c[r], e, tv, mse);
        }
    }

    // block reduce
    #pragma unroll
    for (int off = 16; off > 0; off >>= 1) {
        tv  += __shfl_down_sync(0xffffffffu, tv,  off);
        mse += __shfl_down_sync(0xffffffffu, mse, off);
    }
    __shared__ float stv[8], smse[8];
    if (lane == 0) { stv[wg] = tv; smse[wg] = mse; }
    __syncthreads();
    float bptv = 0.f, bpmse = 0.f;
    if (threadIdx.x == 0) {
        #pragma unroll
        for (int s = 0; s < 8; s++) { bptv += stv[s]; bpmse += smse[s]; }
    }

    // ---- quarter-granular zero protocol (chunk form) ----
    __shared__ int zmask;
    if (threadIdx.x == 0) zmask = 0;
    __syncthreads();                                // all grid reads retired
    if (threadIdx.x == 0) {
        __threadfence();
        int m = 0;
        #pragma unroll
        for (int t = 0; t < 4; ++t) {               // own quarters
            int tgt = 1 + (q > 0 ? 1 : 0) + ((t == 0 && ic > 0) ? 1 : 0);
            if (atomicAdd(&g_done[((p0 + t) << 2) + q], 1) + 1 == tgt)
                m |= 1 << t;
        }
        if (q < 3) {                                // j-next quarters
            #pragma unroll
            for (int t = 0; t < 4; ++t) {
                int tgt = 2 + ((t == 0 && ic > 0) ? 1 : 0);
                if (atomicAdd(&g_done[((p0 + t) << 2) + q + 1], 1) + 1 == tgt)
                    m |= 1 << (4 + t);
            }
        }
        if (ic < 31) {                              // seam quarter
            int tgt = 2 + (q > 0 ? 1 : 0);
            if (atomicAdd(&g_done[((p0 + 4) << 2) + q], 1) + 1 == tgt)
                m |= 1 << 8;
        }
        zmask = m;
    }
    __syncthreads();
    int m = zmask;
    #pragma unroll
    for (int t = 0; t < 4; ++t)
        if (m & (1 << t))       zero_quarter(((p0 + t) << 2) + q,     threadIdx.x);
    #pragma unroll
    for (int t = 0; t < 4; ++t)
        if (m & (1 << (4 + t))) zero_quarter(((p0 + t) << 2) + q + 1, threadIdx.x);
    if (m & (1 << 8))           zero_quarter(((p0 + 4) << 2) + q,     threadIdx.x);

    // ---- publish partials; last reducer of batch finalizes d_out ----
    if (threadIdx.x == 0) {
        atomicAdd(&g_acc_tv[b],  bptv);
        atomicAdd(&g_acc_mse[b], bpmse);
        unsigned prev = atom_acqrel_add(&g_rcnt[b], 1u);
        if (prev == RED_BLK_B - 1) {
            float ttv  = ldf_acquire(&g_acc_tv[b]);
            float tmse = ldf_acquire(&g_acc_mse[b]);
            const float tv_norm  = 1.f / (float)(XS * XS * XS);
            const float mse_norm = 1.f / (float)(2 * XS * XS - 2 * XS);
            d_out[b]         = ttv  * tv_norm;
            d_out[BATCH + b] = tmse * mse_norm;
            g_acc_tv[b]  = 0.f;
            g_acc_mse[b] = 0.f;
            g_rcnt[b] = 0u;
            g_scnt[b] = 0u;
        }
    }
}

// ---------------------------------------------------------------------------
extern "C" void kernel_launch(void* const* d_in, const int* in_sizes, int n_in,
                              void* d_out, int out_size) {
    const int*   indices = (const int*)d_in[0];    // (B, M, 3) int32
    const float* values  = (const float*)d_in[1];  // (B, M) float32
    float* out = (float*)d_out;                    // (2, B) float32

    fused_kernel<<<TOTAL_BLK, 256>>>((const int4*)indices,
                                     (const float4*)values, out);
}

// round 10
// speedup vs baseline: 1.3795x; 1.1363x over previous
#include <cuda_runtime.h>

#define XS    128
#define BATCH 8
#define MPTS  500000
#define NQUART  (BATCH * XS * 4)             // 4096 quarter-planes
#define GRID_ELEMS (BATCH * XS * XS * XS)    // 64 MiB
#define NGROUPS (BATCH * XS / 2)             // 512 plane-pair groups
#define TPB_SCAT (MPTS / 8)                  // 62,500 scatter threads / batch
#define SCAT_BLK_B 245                       // ceil(62500/256), batch-major
#define SCAT_BLKS (BATCH * SCAT_BLK_B)       // 1960
#define RED_BLK_B 256                        // 64 plane-pairs x 4 quarters

// Device scratch (zero-init at load; all counters self-reset per call)
__device__ float g_grid[GRID_ELEMS];
__device__ int   g_done[NQUART];
__device__ unsigned g_scnt[BATCH];
__device__ unsigned g_rcnt[BATCH];
__device__ float g_acc_tv[BATCH];
__device__ float g_acc_mse[BATCH];

// ---- scoped signaling ----
__device__ __forceinline__ void red_release_add(unsigned* p, unsigned v) {
    asm volatile("red.release.gpu.add.u32 [%0], %1;" :: "l"(p), "r"(v) : "memory");
}
__device__ __forceinline__ unsigned atom_acqrel_add(unsigned* p, unsigned v) {
    unsigned r;
    asm volatile("atom.acq_rel.gpu.add.u32 %0, [%1], %2;"
                 : "=r"(r) : "l"(p), "r"(v) : "memory");
    return r;
}
__device__ __forceinline__ unsigned ld_acquire(const unsigned* p) {
    unsigned r;
    asm volatile("ld.acquire.gpu.u32 %0, [%1];" : "=r"(r) : "l"(p) : "memory");
    return r;
}
__device__ __forceinline__ float ldf_acquire(const float* p) {
    float r;
    asm volatile("ld.acquire.gpu.f32 %0, [%1];" : "=f"(r) : "l"(p) : "memory");
    return r;
}

// ---------------------------------------------------------------------------
// Kernel 1 (PDL primary): scatter-add, batch-major blocks. Fires the PDL
// trigger at entry so the reduce grid launches at the start of our last wave.
// ---------------------------------------------------------------------------
__global__ void __launch_bounds__(256) scatter_kernel(
        const int4*   __restrict__ idx4,
        const float4* __restrict__ val4) {
    asm volatile("griddepcontrol.launch_dependents;");

    int b = blockIdx.x / SCAT_BLK_B;
    int t = (blockIdx.x - b * SCAT_BLK_B) * 256 + threadIdx.x;
    if (t < TPB_SCAT) {
        long base = (long)b << 21;
        long p0   = (long)b * MPTS + (long)t * 8;
        int4 a[6];
        #pragma unroll
        for (int s = 0; s < 6; s++) a[s] = __ldcs(&idx4[(p0 * 3) / 4 + s]);
        float4 v0 = __ldcs(&val4[p0 / 4 + 0]);
        float4 v1 = __ldcs(&val4[p0 / 4 + 1]);
        const int* ai = (const int*)a;
        float vals[8] = { v0.x, v0.y, v0.z, v0.w, v1.x, v1.y, v1.z, v1.w };
        #pragma unroll
        for (int s = 0; s < 8; s++) {
            long off = base + ((long)ai[3 * s] << 14) + (ai[3 * s + 1] << 7)
                            + ai[3 * s + 2];
            atomicAdd(&g_grid[off], vals[s]);
        }
    }
    __syncthreads();                            // all REDs program-ordered
    if (threadIdx.x == 0) red_release_add(&g_scnt[b], 1u);
}

// ---- reduce helpers ----
__device__ __forceinline__ void diff4(const float4& a, const float4& b,
                                      float& tv, float& mse) {
    float d0 = b.x - a.x, d1 = b.y - a.y, d2 = b.z - a.z, d3 = b.w - a.w;
    tv  += fabsf(d0) + fabsf(d1) + fabsf(d2) + fabsf(d3);
    mse += d0 * d0 + d1 * d1 + d2 * d2 + d3 * d3;
}
__device__ __forceinline__ void kdiffs(const float4& c, bool cross,
                                       float& tv, float& mse) {
    float d0 = c.y - c.x, d1 = c.z - c.y, d2 = c.w - c.z;
    tv  += fabsf(d0) + fabsf(d1) + fabsf(d2);
    mse += d0 * d0 + d1 * d1 + d2 * d2;
    float nx = __shfl_down_sync(0xffffffffu, c.x, 1);
    if (cross) { float d3 = nx - c.w; tv += fabsf(d3); mse += d3 * d3; }
}
__device__ __forceinline__ void plane_kj(const float4 c[4], const float4& jb,
                                         bool has_jb, bool crossk,
                                         float& tv, float& mse) {
    #pragma unroll
    for (int r = 0; r < 4; r++) kdiffs(c[r], crossk, tv, mse);
    diff4(c[0], c[1], tv, mse);
    diff4(c[1], c[2], tv, mse);
    diff4(c[2], c[3], tv, mse);
    if (has_jb) diff4(c[3], jb, tv, mse);
}
__device__ __forceinline__ void zero_quarter(int qidx, int tid) {
    float4* gw = (float4*)g_grid;
    const long qb = (long)qidx << 10;
    const float4 z = make_float4(0.f, 0.f, 0.f, 0.f);
    #pragma unroll
    for (int it = 0; it < 4; ++it)
        gw[qb + it * 256 + tid] = z;
    if (tid == 0) g_done[qidx] = 0;
}

// ---------------------------------------------------------------------------
// Kernel 2 (PDL secondary): TV+MSE reduce + re-zero, plane-pair blocks
// (R6/R7 tiling, 2048 blocks). NO griddepcontrol.wait — ordering is the
// per-batch release/acquire counter handshake. Blocks batch-major so early
// reducers hit already-complete batches.
// ---------------------------------------------------------------------------
__global__ void __launch_bounds__(256, 6) reduce_zero_kernel(float* __restrict__ d_out) {
    const int rb    = blockIdx.x;                  // 0..2047 batch-major
    const int b     = rb >> 8;                     // 256 blocks per batch
    const int local = rb & 255;
    const int lg    = local >> 2;                  // plane-pair in batch 0..63
    const int q     = local & 3;
    const int p0    = b * XS + lg * 2;             // even global plane
    const int i0    = lg * 2;
    const int lane  = threadIdx.x & 31;
    const int wg    = threadIdx.x >> 5;
    const int jrow0 = q * 32 + wg * 4;
    const bool has_jb = (jrow0 + 4) < XS;
    const bool crossk = (lane != 31);
    const float4* __restrict__ g4 = (const float4*)g_grid;

    // acquire-spin on this batch's scatter completion
    if (threadIdx.x == 0) {
        while (ld_acquire(&g_scnt[b]) < SCAT_BLK_B) __nanosleep(64);
    }
    __syncthreads();

    const long pb0 = (long)p0 << 12;
    const int  fo  = jrow0 * 32 + lane;
    const float4 z = make_float4(0.f, 0.f, 0.f, 0.f);

    float tv = 0.f, mse = 0.f;
    float4 c[4], n[4];

    #pragma unroll
    for (int r = 0; r < 4; r++) c[r] = g4[pb0 + fo + r * 32];
    float4 jb0 = has_jb ? g4[pb0 + fo + 128] : z;
    plane_kj(c, jb0, has_jb, crossk, tv, mse);

    const long pb1 = pb0 + 4096;
    #pragma unroll
    for (int r = 0; r < 4; r++) n[r] = g4[pb1 + fo + r * 32];
    #pragma unroll
    for (int r = 0; r < 4; r++) diff4(c[r], n[r], tv, mse);
    float4 jb1 = has_jb ? g4[pb1 + fo + 128] : z;
    plane_kj(n, jb1, has_jb, crossk, tv, mse);

    const bool has_ext = (i0 < XS - 2);
    if (has_ext) {
        const long pb2 = pb1 + 4096;
        #pragma unroll
        for (int r = 0; r < 4; r++) {
            float4 e = g4[pb2 + fo + r * 32];
            diff4(n[r], e, tv, mse);
        }
    }

    // block reduce
    #pragma unroll
    for (int off = 16; off > 0; off >>= 1) {
        tv  += __shfl_down_sync(0xffffffffu, tv,  off);
        mse += __shfl_down_sync(0xffffffffu, mse, off);
    }
    __shared__ float stv[8], smse[8];
    if (lane == 0) { stv[wg] = tv; smse[wg] = mse; }
    __syncthreads();
    float bptv = 0.f, bpmse = 0.f;
    if (threadIdx.x == 0) {
        #pragma unroll
        for (int s = 0; s < 8; s++) { bptv += stv[s]; bpmse += smse[s]; }
    }

    // ---- quarter-granular zero protocol (R7 form, proven) ----
    __shared__ int zmask;
    if (threadIdx.x == 0) zmask = 0;
    __syncthreads();                                // all grid reads retired
    if (threadIdx.x == 0) {
        __threadfence();
        int m = 0;
        int q0 = (p0 << 2) + q;
        int q1 = ((p0 + 1) << 2) + q;
        int tgt0 = 1 + (q > 0 ? 1 : 0) + (i0 > 0 ? 1 : 0);
        int tgt1 = 1 + (q > 0 ? 1 : 0);
        if (atomicAdd(&g_done[q0], 1) + 1 == tgt0) m |= 1;
        if (atomicAdd(&g_done[q1], 1) + 1 == tgt1) m |= 2;
        if (q < 3) {
            int j0 = (p0 << 2) + q + 1;
            int j1 = ((p0 + 1) << 2) + q + 1;
            if (atomicAdd(&g_done[j0], 1) + 1 == 2 + (i0 > 0 ? 1 : 0)) m |= 4;
            if (atomicAdd(&g_done[j1], 1) + 1 == 2) m |= 8;
        }
        if (has_ext) {
            int e0 = ((p0 + 2) << 2) + q;
            if (atomicAdd(&g_done[e0], 1) + 1 == 2 + (q > 0 ? 1 : 0)) m |= 16;
        }
        zmask = m;
    }
    __syncthreads();
    int m = zmask;
    if (m & 1)  zero_quarter((p0 << 2) + q,           threadIdx.x);
    if (m & 2)  zero_quarter(((p0 + 1) << 2) + q,     threadIdx.x);
    if (m & 4)  zero_quarter((p0 << 2) + q + 1,       threadIdx.x);
    if (m & 8)  zero_quarter(((p0 + 1) << 2) + q + 1, threadIdx.x);
    if (m & 16) zero_quarter(((p0 + 2) << 2) + q,     threadIdx.x);

    // ---- publish partials; last reducer of batch finalizes d_out ----
    if (threadIdx.x == 0) {
        atomicAdd(&g_acc_tv[b],  bptv);
        atomicAdd(&g_acc_mse[b], bpmse);
        unsigned prev = atom_acqrel_add(&g_rcnt[b], 1u);
        if (prev == RED_BLK_B - 1) {
            float ttv  = ldf_acquire(&g_acc_tv[b]);
            float tmse = ldf_acquire(&g_acc_mse[b]);
            const float tv_norm  = 1.f / (float)(XS * XS * XS);
            const float mse_norm = 1.f / (float)(2 * XS * XS - 2 * XS);
            d_out[b]         = ttv  * tv_norm;
            d_out[BATCH + b] = tmse * mse_norm;
            g_acc_tv[b]  = 0.f;
            g_acc_mse[b] = 0.f;
            g_rcnt[b] = 0u;
            g_scnt[b] = 0u;
        }
    }
}

// ---------------------------------------------------------------------------
extern "C" void kernel_launch(void* const* d_in, const int* in_sizes, int n_in,
                              void* d_out, int out_size) {
    const int*   indices = (const int*)d_in[0];    // (B, M, 3) int32
    const float* values  = (const float*)d_in[1];  // (B, M) float32
    float* out = (float*)d_out;                    // (2, B) float32

    // Primary: scatter (normal launch; fires PDL trigger at block entry)
    scatter_kernel<<<SCAT_BLKS, 256>>>((const int4*)indices,
                                       (const float4*)values);

    // Secondary: reduce with programmatic stream serialization (overlaps the
    // primary's drain; self-orders via the per-batch counter handshake)
    cudaLaunchAttribute attrs[1];
    attrs[0].id = cudaLaunchAttributeProgrammaticStreamSerialization;
    attrs[0].val.programmaticStreamSerializationAllowed = 1;
    cudaLaunchConfig_t cfg = {};
    cfg.gridDim  = dim3(BATCH * RED_BLK_B);        // 2048
    cfg.blockDim = dim3(256);
    cfg.dynamicSmemBytes = 0;
    cfg.stream = 0;
    cfg.attrs = attrs;
    cfg.numAttrs = 1;
    cudaLaunchKernelEx(&cfg, reduce_zero_kernel, out);
}